// round 10
// baseline (speedup 1.0000x reference)
#include <cuda_runtime.h>
#include <cstdint>

namespace {

typedef unsigned long long ull;

constexpr int S  = 200;
constexpr int D  = 64;
constexpr int H1 = 64;
constexpr int H2 = 16;
constexpr int THREADS = 256;
constexpr int CHUNK = 100;              // positions per chunk (2 chunks)
constexpr float EPS = 1e-9f;

constexpr int KT_STRIDE = 204;          // floats per kT row (16B-aligned rows)
constexpr int H1S_STRIDE = 68;          // floats per h1 row (16B-aligned, near-conflict-free)

// ---- dynamic smem layout (float offsets) ----
constexpr int KT_OFF  = 0;                           // 64*204 = 13056
constexpr int MS_OFF  = KT_OFF + D * KT_STRIDE;      // 64*64  = 4096  (alias: stage-3 reduction)
constexpr int H1S_OFF = MS_OFF + D * H1;             // 100*68 = 6800  (fp32, per-chunk)
constexpr int W2_OFF  = H1S_OFF + CHUNK * H1S_STRIDE;// 1024
constexpr int QS_OFF  = W2_OFF + H1 * H2;            // 64
constexpr int QA_OFF  = QS_OFF + D;                  // 64
constexpr int WT_OFF  = QA_OFF + H1;                 // 200
constexpr int P1_OFF  = WT_OFF + S;                  // 192 (alpha1, mean1, rstd1)
constexpr int P2_OFF  = P1_OFF + 3 * H1;             // 48
constexpr int W3_OFF  = P2_OFF + 48;                 // 16
constexpr int SMEM_FLOATS = W3_OFF + H2;             // 25560
constexpr int SMEM_BYTES  = SMEM_FLOATS * 4;         // 102240 B -> 2 CTAs/SM

__device__ __forceinline__ void ffma2(ull& d, ull a, ull b) {
    asm("fma.rn.f32x2 %0, %1, %2, %0;" : "+l"(d) : "l"(a), "l"(b));
}
__device__ __forceinline__ ull pack2(float lo, float hi) {
    ull r; asm("mov.b64 %0, {%1, %2};" : "=l"(r) : "f"(lo), "f"(hi)); return r;
}
__device__ __forceinline__ float2 unpack2(ull v) {
    float2 r; asm("mov.b64 {%0, %1}, %2;" : "=f"(r.x), "=f"(r.y) : "l"(v)); return r;
}

__device__ __forceinline__ float sigmoidf_fast(float z) {
    return __fdividef(1.0f, 1.0f + __expf(-z));
}
// Dice at inference: x * (alpha + sigmoid((x-mean)*rstd) * (1 - alpha))
__device__ __forceinline__ float dicef(float x, float alpha, float mean, float rstd) {
    float s = sigmoidf_fast((x - mean) * rstd);
    return x * (alpha + s * (1.0f - alpha));
}

__global__ void __launch_bounds__(THREADS, 2)
din_pool_kernel(const float* __restrict__ query, const float* __restrict__ key,
                const int*   __restrict__ seqlen,
                const float* __restrict__ W1, const float* __restrict__ a1,
                const float* __restrict__ m1, const float* __restrict__ v1,
                const float* __restrict__ W2, const float* __restrict__ a2,
                const float* __restrict__ m2, const float* __restrict__ v2,
                const float* __restrict__ W3, float* __restrict__ out)
{
    extern __shared__ float smf[];
    float* kT  = smf + KT_OFF;
    float* Msm = smf + MS_OFF;
    float* h1s = smf + H1S_OFF;
    float* W2s = smf + W2_OFF;
    float* qs  = smf + QS_OFF;
    float* qa  = smf + QA_OFF;
    float* wts = smf + WT_OFF;
    float* P1  = smf + P1_OFF;
    float* P2  = smf + P2_OFF;
    float* W3s = smf + W3_OFF;
    float* red = Msm;   // alias: stage-3 partials (M fully consumed by then)

    const int b = blockIdx.x;
    const int t = threadIdx.x;
    const int L = seqlen[b];

    // ================= phase A: params + transposed K copy =================
    if (t < D / 4)
        reinterpret_cast<float4*>(qs)[t] =
            reinterpret_cast<const float4*>(query + (size_t)b * D)[t];

    reinterpret_cast<float4*>(W2s)[t] = reinterpret_cast<const float4*>(W2)[t]; // exactly 256 float4

    if (t < H1) {
        P1[t]          = a1[t];
        P1[H1 + t]     = m1[t];
        P1[2 * H1 + t] = rsqrtf(v1[t] + EPS);
    }
    if (t < H2) {
        P2[t]      = a2[t];
        P2[16 + t] = m2[t];
        P2[32 + t] = rsqrtf(v2[t] + EPS);
        W3s[t]     = W3[t];
    }

    // K transpose: lane owns channel dl, strides over 50 positions.
    // LDG: 32 consecutive lanes -> 128B coalesced. STS: <=4-way conflict (acceptable).
    {
        const int dl = t & 63, g4 = t >> 6;
        const float* kg = key + (size_t)b * S * D + dl;
        float* kr = kT + dl * KT_STRIDE;
        const int pend = g4 * 50 + 50;
        #pragma unroll 5
        for (int p = g4 * 50; p < pend; ++p)
            kr[p] = kg[(size_t)p * D];
    }
    __syncthreads();

    // ================= phase B: folded M (64x64) and qa =================
    // att@W1 = q@(W1a+W1c) + k@(W1b - W1c + diag(q)@W1d)
    for (int i = t; i < (D * H1) / 4; i += THREADS) {
        int d = i >> 4, hq = i & 15;
        float4 wb = reinterpret_cast<const float4*>(W1 + (size_t)(D     + d) * H1)[hq];
        float4 wc = reinterpret_cast<const float4*>(W1 + (size_t)(2 * D + d) * H1)[hq];
        float4 wd = reinterpret_cast<const float4*>(W1 + (size_t)(3 * D + d) * H1)[hq];
        float qd = qs[d];
        float4 m;
        m.x = wb.x - wc.x + qd * wd.x;
        m.y = wb.y - wc.y + qd * wd.y;
        m.z = wb.z - wc.z + qd * wd.z;
        m.w = wb.w - wc.w + qd * wd.w;
        reinterpret_cast<float4*>(Msm + d * H1)[hq] = m;
    }
    if (t < H1) {
        float acc = 0.0f;
        #pragma unroll 8
        for (int d = 0; d < D; ++d)
            acc = fmaf(qs[d], W1[(size_t)d * H1 + t] + W1[(size_t)(2 * D + d) * H1 + t], acc);
        qa[t] = acc;
    }
    __syncthreads();

    // ================= chunked stages 1+2 (fp32 h1 throughout) =================
    #pragma unroll 1
    for (int c = 0; c < 2; ++c) {
        // ---- stage 1: h1 = dice(K @ M + qa), 4 pos x 8 ch per thread ----
        if (t < 200) {
            const int pg = t >> 3, hg = t & 7;
            const int p0 = pg * 4;          // local position within chunk
            const int h0 = hg * 8;

            ull acc[2][8];
            #pragma unroll
            for (int i = 0; i < 2; ++i)
                #pragma unroll
                for (int h = 0; h < 8; ++h) acc[i][h] = 0ull;

            const float* kbase = kT + c * CHUNK + p0;
            const float* mbase = Msm + h0;

            #pragma unroll 4
            for (int d = 0; d < D; ++d) {
                ulonglong2 ka = *reinterpret_cast<const ulonglong2*>(kbase + d * KT_STRIDE);
                float4 m0  = *reinterpret_cast<const float4*>(mbase + d * H1);
                float4 m1v = *reinterpret_cast<const float4*>(mbase + d * H1 + 4);
                ull md[8];
                md[0] = pack2(m0.x,  m0.x);  md[1] = pack2(m0.y,  m0.y);
                md[2] = pack2(m0.z,  m0.z);  md[3] = pack2(m0.w,  m0.w);
                md[4] = pack2(m1v.x, m1v.x); md[5] = pack2(m1v.y, m1v.y);
                md[6] = pack2(m1v.z, m1v.z); md[7] = pack2(m1v.w, m1v.w);
                #pragma unroll
                for (int h = 0; h < 8; ++h) {
                    ffma2(acc[0][h], ka.x, md[h]);   // positions p0, p0+1
                    ffma2(acc[1][h], ka.y, md[h]);   // positions p0+2, p0+3
                }
            }

            // epilogue: + qa, dice1, fp32 store
            float a1v[8], muv[8], rsv[8], qv[8];
            #pragma unroll
            for (int h = 0; h < 8; ++h) {
                a1v[h] = P1[h0 + h];
                muv[h] = P1[H1 + h0 + h];
                rsv[h] = P1[2 * H1 + h0 + h];
                qv[h]  = qa[h0 + h];
            }
            #pragma unroll
            for (int pp = 0; pp < 2; ++pp) {
                float2 v[8];
                #pragma unroll
                for (int h = 0; h < 8; ++h) v[h] = unpack2(acc[pp][h]);

                float ya[8], yb[8];
                #pragma unroll
                for (int h = 0; h < 8; ++h) {
                    ya[h] = dicef(v[h].x + qv[h], a1v[h], muv[h], rsv[h]);  // pos p0+2pp
                    yb[h] = dicef(v[h].y + qv[h], a1v[h], muv[h], rsv[h]);  // pos p0+2pp+1
                }
                const int pA = p0 + 2 * pp;
                float4* rowA = reinterpret_cast<float4*>(h1s + pA * H1S_STRIDE + h0);
                float4* rowB = reinterpret_cast<float4*>(h1s + (pA + 1) * H1S_STRIDE + h0);
                rowA[0] = make_float4(ya[0], ya[1], ya[2], ya[3]);
                rowA[1] = make_float4(ya[4], ya[5], ya[6], ya[7]);
                rowB[0] = make_float4(yb[0], yb[1], yb[2], yb[3]);
                rowB[1] = make_float4(yb[4], yb[5], yb[6], yb[7]);
            }
        }
        __syncthreads();

        // ---- stage 2: h2 = dice(h1 @ W2), score, weight (round-1 proven) ----
        if (t < CHUNK) {
            const int p = c * CHUNK + t;           // global position
            const float* h1p = h1s + t * H1S_STRIDE;
            float acc[H2];
            #pragma unroll
            for (int j = 0; j < H2; ++j) acc[j] = 0.0f;

            #pragma unroll
            for (int hh = 0; hh < H1; hh += 4) {
                float4 hv = *reinterpret_cast<const float4*>(h1p + hh);
                float hvals[4] = {hv.x, hv.y, hv.z, hv.w};
                #pragma unroll
                for (int u = 0; u < 4; ++u) {
                    const float4* wrow = reinterpret_cast<const float4*>(W2s + (hh + u) * H2);
                    float4 w0 = wrow[0], w1 = wrow[1], w2v = wrow[2], w3v = wrow[3]; // broadcast
                    float hval = hvals[u];
                    acc[0]  = fmaf(hval, w0.x,  acc[0]);
                    acc[1]  = fmaf(hval, w0.y,  acc[1]);
                    acc[2]  = fmaf(hval, w0.z,  acc[2]);
                    acc[3]  = fmaf(hval, w0.w,  acc[3]);
                    acc[4]  = fmaf(hval, w1.x,  acc[4]);
                    acc[5]  = fmaf(hval, w1.y,  acc[5]);
                    acc[6]  = fmaf(hval, w1.z,  acc[6]);
                    acc[7]  = fmaf(hval, w1.w,  acc[7]);
                    acc[8]  = fmaf(hval, w2v.x, acc[8]);
                    acc[9]  = fmaf(hval, w2v.y, acc[9]);
                    acc[10] = fmaf(hval, w2v.z, acc[10]);
                    acc[11] = fmaf(hval, w2v.w, acc[11]);
                    acc[12] = fmaf(hval, w3v.x, acc[12]);
                    acc[13] = fmaf(hval, w3v.y, acc[13]);
                    acc[14] = fmaf(hval, w3v.z, acc[14]);
                    acc[15] = fmaf(hval, w3v.w, acc[15]);
                }
            }
            float score = 0.0f;
            #pragma unroll
            for (int j = 0; j < H2; ++j) {
                float hv2 = dicef(acc[j], P2[j], P2[16 + j], P2[32 + j]);
                score = fmaf(hv2, W3s[j], score);
            }
            // masked score -> sigmoid(NEG_INF) == 0 exactly
            wts[p] = (p < L) ? sigmoidf_fast(score) : 0.0f;
        }
        __syncthreads();
    }

    // ================= stage 3: out = sum_p wts[p] * K[p,:] (from kT) =================
    {
        const int dd = t & 63, g = t >> 6;
        const int start = g * 52;
        const int n4 = (g == 3) ? 11 : 13;   // 52,52,52,44 positions
        const float4* kr = reinterpret_cast<const float4*>(kT + dd * KT_STRIDE + start);
        const float4* wr = reinterpret_cast<const float4*>(wts + start);
        float acc = 0.0f;
        #pragma unroll 13
        for (int i = 0; i < n4; ++i) {
            float4 kv = kr[i];
            float4 wv = wr[i];
            acc = fmaf(wv.x, kv.x, acc);
            acc = fmaf(wv.y, kv.y, acc);
            acc = fmaf(wv.z, kv.z, acc);
            acc = fmaf(wv.w, kv.w, acc);
        }
        red[g * D + dd] = acc;
    }
    __syncthreads();
    if (t < D)
        out[(size_t)b * D + t] = (red[t] + red[D + t]) + (red[2 * D + t] + red[3 * D + t]);
}

} // anonymous namespace

extern "C" void kernel_launch(void* const* d_in, const int* in_sizes, int n_in,
                              void* d_out, int out_size)
{
    const float* query = (const float*)d_in[0];
    const float* key   = (const float*)d_in[1];
    const int*   sl    = (const int*)  d_in[2];
    const float* W1    = (const float*)d_in[3];
    const float* a1    = (const float*)d_in[4];
    const float* m1    = (const float*)d_in[5];
    const float* v1    = (const float*)d_in[6];
    const float* W2    = (const float*)d_in[7];
    const float* a2    = (const float*)d_in[8];
    const float* m2    = (const float*)d_in[9];
    const float* v2    = (const float*)d_in[10];
    const float* W3    = (const float*)d_in[11];
    float* out = (float*)d_out;

    const int B = in_sizes[0] / D;   // 2048

    cudaFuncSetAttribute(din_pool_kernel,
                         cudaFuncAttributeMaxDynamicSharedMemorySize, SMEM_BYTES);
    din_pool_kernel<<<B, THREADS, SMEM_BYTES>>>(query, key, sl,
                                                W1, a1, m1, v1,
                                                W2, a2, m2, v2,
                                                W3, out);
}

// round 16
// speedup vs baseline: 1.5208x; 1.5208x over previous
#include <cuda_runtime.h>
#include <cuda_bf16.h>
#include <cstdint>

namespace {

constexpr int S  = 200;
constexpr int D  = 64;
constexpr int H1 = 64;
constexpr int H2 = 16;
constexpr int THREADS = 256;
constexpr int CH = 128;                 // positions per chunk (2 chunks cover 200 padded to 256)
constexpr float EPS = 1e-9f;

constexpr int H1S_STRIDE = 68;          // fp32 h1 row stride (16B-aligned, conflict-free float4)
constexpr int MT_STRIDE  = 72;          // bf16 Mt row stride (144B -> conflict-free frag loads)

// ---- smem layout (float offsets) ----
constexpr int H1S_OFF = 0;                            // 128*68 = 8704
constexpr int W2S_OFF = H1S_OFF + CH * H1S_STRIDE;    // 1024
constexpr int QS_OFF  = W2S_OFF + H1 * H2;            // 64
constexpr int QA_OFF  = QS_OFF + D;                   // 64
constexpr int WTS_OFF = QA_OFF + H1;                  // 200
constexpr int P1_OFF  = WTS_OFF + S;                  // 192
constexpr int P2_OFF  = P1_OFF + 3 * H1;              // 48
constexpr int W3S_OFF = P2_OFF + 48;                  // 16
constexpr int RED_OFF = W3S_OFF + H2;                 // 256
constexpr int MTH_OFF = RED_OFF + 256;                // 64*72 bf16 = 2304 floats
constexpr int MTL_OFF = MTH_OFF + (H1 * MT_STRIDE) / 2;
constexpr int SMEM_FLOATS = MTL_OFF + (H1 * MT_STRIDE) / 2;   // 15176
constexpr int SMEM_BYTES  = SMEM_FLOATS * 4;                  // 60704 B -> 2 CTAs/SM

__device__ __forceinline__ float sigmoidf_fast(float z) {
    return __fdividef(1.0f, 1.0f + __expf(-z));
}
__device__ __forceinline__ float dicef(float x, float alpha, float mean, float rstd) {
    float s = sigmoidf_fast((x - mean) * rstd);
    return x * (alpha + s * (1.0f - alpha));
}

// Convert float2 -> bf16x2 (hi) + bf16x2 (residual lo). .x lands in low half.
__device__ __forceinline__ uint32_t split_bf16x2(float2 v, uint32_t& lo) {
    __nv_bfloat162 hb = __float22bfloat162_rn(v);
    float2 hf = __bfloat1622float2(hb);
    float2 rv = make_float2(v.x - hf.x, v.y - hf.y);
    __nv_bfloat162 lb = __float22bfloat162_rn(rv);
    lo = *reinterpret_cast<uint32_t*>(&lb);
    return *reinterpret_cast<uint32_t*>(&hb);
}

__device__ __forceinline__ void mma_bf16(float d[4], uint32_t a0, uint32_t a1,
                                         uint32_t a2, uint32_t a3,
                                         uint32_t b0, uint32_t b1) {
    asm volatile(
        "mma.sync.aligned.m16n8k16.row.col.f32.bf16.bf16.f32 "
        "{%0,%1,%2,%3}, {%4,%5,%6,%7}, {%8,%9}, {%0,%1,%2,%3};"
        : "+f"(d[0]), "+f"(d[1]), "+f"(d[2]), "+f"(d[3])
        : "r"(a0), "r"(a1), "r"(a2), "r"(a3), "r"(b0), "r"(b1));
}

__global__ void __launch_bounds__(THREADS, 2)
din_pool_kernel(const float* __restrict__ query, const float* __restrict__ key,
                const int*   __restrict__ seqlen,
                const float* __restrict__ W1, const float* __restrict__ a1,
                const float* __restrict__ m1, const float* __restrict__ v1,
                const float* __restrict__ W2, const float* __restrict__ a2,
                const float* __restrict__ m2, const float* __restrict__ v2,
                const float* __restrict__ W3, float* __restrict__ out)
{
    extern __shared__ float smf[];
    float*         h1s = smf + H1S_OFF;
    float*         W2s = smf + W2S_OFF;
    float*         qs  = smf + QS_OFF;
    float*         qa  = smf + QA_OFF;
    float*         wts = smf + WTS_OFF;
    float*         P1  = smf + P1_OFF;
    float*         P2  = smf + P2_OFF;
    float*         W3s = smf + W3S_OFF;
    float*         red = smf + RED_OFF;
    __nv_bfloat16* MtH = reinterpret_cast<__nv_bfloat16*>(smf + MTH_OFF);
    __nv_bfloat16* MtL = reinterpret_cast<__nv_bfloat16*>(smf + MTL_OFF);

    const int b   = blockIdx.x;
    const int t   = threadIdx.x;
    const int wid = t >> 5;
    const int lid = t & 31;
    const int L   = seqlen[b];

    // ================= phase A: params =================
    if (t < D / 4)
        reinterpret_cast<float4*>(qs)[t] =
            reinterpret_cast<const float4*>(query + (size_t)b * D)[t];

    reinterpret_cast<float4*>(W2s)[t] = reinterpret_cast<const float4*>(W2)[t]; // exactly 256

    if (t < H1) {
        P1[t]          = a1[t];
        P1[H1 + t]     = m1[t];
        P1[2 * H1 + t] = rsqrtf(v1[t] + EPS);
    }
    if (t < H2) {
        P2[t]      = a2[t];
        P2[16 + t] = m2[t];
        P2[32 + t] = rsqrtf(v2[t] + EPS);
        W3s[t]     = W3[t];
    }
    __syncthreads();   // qs visible

    // ================= phase B: folded M -> Mt[h][d] bf16 hi/lo, + qa =================
    // att@W1 = q@(W1a+W1c) + k@(W1b - W1c + diag(q)@W1d)
    #pragma unroll 4
    for (int i = t; i < D * H1; i += THREADS) {
        const int d = i >> 6, h = i & 63;
        float wb = W1[(size_t)(D     + d) * H1 + h];
        float wc = W1[(size_t)(2 * D + d) * H1 + h];
        float wd = W1[(size_t)(3 * D + d) * H1 + h];
        float mv = wb - wc + qs[d] * wd;
        __nv_bfloat16 hb = __float2bfloat16(mv);
        __nv_bfloat16 lb = __float2bfloat16(mv - __bfloat162float(hb));
        MtH[h * MT_STRIDE + d] = hb;
        MtL[h * MT_STRIDE + d] = lb;
    }
    if (t < H1) {
        float acc = 0.0f;
        #pragma unroll 8
        for (int d = 0; d < D; ++d)
            acc = fmaf(qs[d], W1[(size_t)d * H1 + t] + W1[(size_t)(2 * D + d) * H1 + t], acc);
        qa[t] = acc;
    }
    __syncthreads();

    // ================= chunked stage 1 (mma.sync) + stage 2 =================
    const float* kgb = key + (size_t)b * S * D;

    #pragma unroll 1
    for (int c = 0; c < 2; ++c) {
        // ---- stage 1: warp computes 16 positions x 64 channels via bf16-split mma ----
        const int pbase = c * CH + wid * 16;
        float dacc[8][4];
        #pragma unroll
        for (int n = 0; n < 8; ++n)
            #pragma unroll
            for (int j = 0; j < 4; ++j) dacc[n][j] = 0.0f;

        const int r0 = min(pbase + (lid >> 2), S - 1);       // clamp: OOB rows discarded later
        const int r1 = min(pbase + 8 + (lid >> 2), S - 1);
        const int qc = (lid & 3) * 2;

        #pragma unroll
        for (int ks = 0; ks < 4; ++ks) {
            const int k0 = ks * 16;
            // A fragments from GMEM, split hi/lo in registers
            float2 x0 = *reinterpret_cast<const float2*>(kgb + (size_t)r0 * D + k0 + qc);
            float2 x1 = *reinterpret_cast<const float2*>(kgb + (size_t)r1 * D + k0 + qc);
            float2 x2 = *reinterpret_cast<const float2*>(kgb + (size_t)r0 * D + k0 + qc + 8);
            float2 x3 = *reinterpret_cast<const float2*>(kgb + (size_t)r1 * D + k0 + qc + 8);
            uint32_t aL0, aL1, aL2, aL3;
            uint32_t aH0 = split_bf16x2(x0, aL0);
            uint32_t aH1 = split_bf16x2(x1, aL1);
            uint32_t aH2 = split_bf16x2(x2, aL2);
            uint32_t aH3 = split_bf16x2(x3, aL3);

            const int brow = (lid >> 2);     // B col (h1 channel within n-tile)
            const int bk   = k0 + qc;        // B k index (pair)
            #pragma unroll
            for (int n = 0; n < 8; ++n) {
                const int hrow = n * 8 + brow;
                uint32_t bH0 = *reinterpret_cast<const uint32_t*>(MtH + hrow * MT_STRIDE + bk);
                uint32_t bH1 = *reinterpret_cast<const uint32_t*>(MtH + hrow * MT_STRIDE + bk + 8);
                uint32_t bL0 = *reinterpret_cast<const uint32_t*>(MtL + hrow * MT_STRIDE + bk);
                uint32_t bL1 = *reinterpret_cast<const uint32_t*>(MtL + hrow * MT_STRIDE + bk + 8);
                mma_bf16(dacc[n], aH0, aH1, aH2, aH3, bH0, bH1);   // Khi*Mhi
                mma_bf16(dacc[n], aH0, aH1, aH2, aH3, bL0, bL1);   // Khi*Mlo
                mma_bf16(dacc[n], aL0, aL1, aL2, aL3, bH0, bH1);   // Klo*Mhi
            }
        }

        // ---- epilogue: +qa, dice1, store fp32 h1 chunk ----
        {
            const int pL0 = wid * 16 + (lid >> 2);
            const int pL1 = pL0 + 8;
            #pragma unroll
            for (int n = 0; n < 8; ++n) {
                const int c0 = n * 8 + qc;
                float2 qa2 = *reinterpret_cast<const float2*>(qa + c0);
                float2 al2 = *reinterpret_cast<const float2*>(P1 + c0);
                float2 mu2 = *reinterpret_cast<const float2*>(P1 + H1 + c0);
                float2 rs2 = *reinterpret_cast<const float2*>(P1 + 2 * H1 + c0);
                float2 y0, y1;
                y0.x = dicef(dacc[n][0] + qa2.x, al2.x, mu2.x, rs2.x);
                y0.y = dicef(dacc[n][1] + qa2.y, al2.y, mu2.y, rs2.y);
                y1.x = dicef(dacc[n][2] + qa2.x, al2.x, mu2.x, rs2.x);
                y1.y = dicef(dacc[n][3] + qa2.y, al2.y, mu2.y, rs2.y);
                *reinterpret_cast<float2*>(h1s + pL0 * H1S_STRIDE + c0) = y0;
                *reinterpret_cast<float2*>(h1s + pL1 * H1S_STRIDE + c0) = y1;
            }
        }
        __syncthreads();

        // ---- stage 2: h2 = dice(h1 @ W2), score, weight (R10-proven) ----
        if (t < CH) {
            const int p = c * CH + t;
            if (p < S) {
                const float* h1p = h1s + t * H1S_STRIDE;
                float acc[H2];
                #pragma unroll
                for (int j = 0; j < H2; ++j) acc[j] = 0.0f;

                #pragma unroll
                for (int hh = 0; hh < H1; hh += 4) {
                    float4 hv = *reinterpret_cast<const float4*>(h1p + hh);
                    float hvals[4] = {hv.x, hv.y, hv.z, hv.w};
                    #pragma unroll
                    for (int u = 0; u < 4; ++u) {
                        const float4* wrow = reinterpret_cast<const float4*>(W2s + (hh + u) * H2);
                        float4 w0 = wrow[0], w1v = wrow[1], w2v = wrow[2], w3v = wrow[3];
                        float hval = hvals[u];
                        acc[0]  = fmaf(hval, w0.x,  acc[0]);
                        acc[1]  = fmaf(hval, w0.y,  acc[1]);
                        acc[2]  = fmaf(hval, w0.z,  acc[2]);
                        acc[3]  = fmaf(hval, w0.w,  acc[3]);
                        acc[4]  = fmaf(hval, w1v.x, acc[4]);
                        acc[5]  = fmaf(hval, w1v.y, acc[5]);
                        acc[6]  = fmaf(hval, w1v.z, acc[6]);
                        acc[7]  = fmaf(hval, w1v.w, acc[7]);
                        acc[8]  = fmaf(hval, w2v.x, acc[8]);
                        acc[9]  = fmaf(hval, w2v.y, acc[9]);
                        acc[10] = fmaf(hval, w2v.z, acc[10]);
                        acc[11] = fmaf(hval, w2v.w, acc[11]);
                        acc[12] = fmaf(hval, w3v.x, acc[12]);
                        acc[13] = fmaf(hval, w3v.y, acc[13]);
                        acc[14] = fmaf(hval, w3v.z, acc[14]);
                        acc[15] = fmaf(hval, w3v.w, acc[15]);
                    }
                }
                float score = 0.0f;
                #pragma unroll
                for (int j = 0; j < H2; ++j) {
                    float hv2 = dicef(acc[j], P2[j], P2[16 + j], P2[32 + j]);
                    score = fmaf(hv2, W3s[j], score);
                }
                wts[p] = (p < L) ? sigmoidf_fast(score) : 0.0f;   // sigmoid(NEG_INF)==0
            }
        }
        __syncthreads();
    }

    // ================= stage 3: out = sum_p wts[p] * K[p,:] (coalesced GMEM, L2-hot) ====
    {
        const int dd = t & 63, g = t >> 6;
        const float* kp = kgb + dd;
        float acc = 0.0f;
        #pragma unroll 5
        for (int p = g; p < S; p += 4)
            acc = fmaf(wts[p], kp[(size_t)p * D], acc);
        red[g * D + dd] = acc;
    }
    __syncthreads();
    if (t < D)
        out[(size_t)b * D + t] = (red[t] + red[D + t]) + (red[2 * D + t] + red[3 * D + t]);
}

} // anonymous namespace

extern "C" void kernel_launch(void* const* d_in, const int* in_sizes, int n_in,
                              void* d_out, int out_size)
{
    const float* query = (const float*)d_in[0];
    const float* key   = (const float*)d_in[1];
    const int*   sl    = (const int*)  d_in[2];
    const float* W1    = (const float*)d_in[3];
    const float* a1    = (const float*)d_in[4];
    const float* m1    = (const float*)d_in[5];
    const float* v1    = (const float*)d_in[6];
    const float* W2    = (const float*)d_in[7];
    const float* a2    = (const float*)d_in[8];
    const float* m2    = (const float*)d_in[9];
    const float* v2    = (const float*)d_in[10];
    const float* W3    = (const float*)d_in[11];
    float* out = (float*)d_out;

    const int B = in_sizes[0] / D;   // 2048

    cudaFuncSetAttribute(din_pool_kernel,
                         cudaFuncAttributeMaxDynamicSharedMemorySize, SMEM_BYTES);
    din_pool_kernel<<<B, THREADS, SMEM_BYTES>>>(query, key, sl,
                                                W1, a1, m1, v1,
                                                W2, a2, m2, v2,
                                                W3, out);
}